// round 5
// baseline (speedup 1.0000x reference)
#include <cuda_runtime.h>
#include <cstdint>

#define NN 100000
#define NE 1600000
#define NEG_SLOPE 0.2f
#define BN_EPS 1e-5f

// ---------------- scratch (static __device__, no allocation) ----------------
__device__ __align__(16) float g_h[(size_t)NN * 128];   // GEMM output [N,4,32]
__device__ __align__(16) float g_y[(size_t)NN * 32];    // per-layer node features
__device__ __align__(16) float g_alS[(size_t)NN * 4];
__device__ __align__(16) float g_alD[(size_t)NN * 4];
__device__ int g_deg[NN];
__device__ int g_rowptr[NN + 1];
__device__ int g_cursor[NN];
__device__ int g_csr_src[NE];
__device__ float g_bn[2 * 32 * 32];                     // strided sums / sumsq
__device__ float g_scale[32];
__device__ float g_shift[32];

__device__ __forceinline__ float leaky(float e) {
    return e >= 0.f ? e : NEG_SLOPE * e;
}

// ---------------- CSR build ----------------
__global__ void hist_k(const int* __restrict__ dst, int* __restrict__ deg) {
    int i = blockIdx.x * blockDim.x + threadIdx.x;
    if (i < NE) atomicAdd(&deg[dst[i]], 1);
}

// single block, 1024 threads: chunked exclusive scan of deg -> rowptr, cursor
__global__ void scan_k(const int* __restrict__ deg, int* __restrict__ rowptr,
                       int* __restrict__ cursor) {
    __shared__ int sc[1024];
    const int tid = threadIdx.x;
    const int CH = (NN + 1023) / 1024;  // 98
    const int base = tid * CH;
    int s = 0;
    for (int i = 0; i < CH; ++i) {
        int idx = base + i;
        if (idx < NN) s += deg[idx];
    }
    sc[tid] = s;
    __syncthreads();
    for (int off = 1; off < 1024; off <<= 1) {
        int v = (tid >= off) ? sc[tid - off] : 0;
        __syncthreads();
        sc[tid] += v;
        __syncthreads();
    }
    int run = sc[tid] - s;
    for (int i = 0; i < CH; ++i) {
        int idx = base + i;
        if (idx < NN) {
            rowptr[idx] = run;
            cursor[idx] = run;
            run += deg[idx];
        }
    }
    if (tid == 1023) rowptr[NN] = sc[1023];
}

__global__ void scatter_build_k(const int* __restrict__ src, const int* __restrict__ dst,
                                int* __restrict__ cursor, int* __restrict__ csr_src) {
    int i = blockIdx.x * blockDim.x + threadIdx.x;
    if (i >= NE) return;
    int p = atomicAdd(&cursor[dst[i]], 1);
    csr_src[p] = src[i];
}

// ---------------- GEMM + attention logits (fused prev-layer BN+ReLU) ----------------
// 512 threads = 4 groups x 128; 128 nodes/block (4 t-iters x 4 groups x 8 nodes)
#define TM 8
#define NG 4
template<int F>
__global__ void __launch_bounds__(512, 2)
gemm_al(const float* __restrict__ x,     // [N,F]
        const float* __restrict__ W,     // [F,128]
        const float* __restrict__ aS,    // [128]
        const float* __restrict__ aD,    // [128]
        const float* __restrict__ scale, // [F] or null
        const float* __restrict__ shift, // [F] or null
        float* __restrict__ h,           // [N,128]
        float* __restrict__ alS,         // [N,4]
        float* __restrict__ alD,         // [N,4]
        int useBN)
{
    extern __shared__ float sm[];
    float* sW = sm;                               // F*128
    const int tid = threadIdx.x;
    const int f = tid & 127;
    const int grp = tid >> 7;
    float* sx = sm + F * 128 + grp * TM * F;      // per-group staging
    const int lane = tid & 31;
    const int head = f >> 5;

    for (int i = tid; i < F * 128; i += 512) sW[i] = W[i];
    const float as = aS[f];
    const float ad = aD[f];
    __syncthreads();

    const int nodeBase = blockIdx.x * 128;
    const float4* sx4 = reinterpret_cast<const float4*>(sx);

    for (int t = 0; t < 4; ++t) {
        int n0 = nodeBase + (t * NG + grp) * TM;
        __syncthreads();
        for (int i = f; i < TM * F; i += 128) {
            int m = i / F, k = i - m * F;
            int n = n0 + m;
            float v = 0.f;
            if (n < NN) {
                v = x[(size_t)n * F + k];
                if (useBN) v = fmaxf(fmaf(v, scale[k], shift[k]), 0.f);
            }
            sx[i] = v;
        }
        __syncthreads();

        float acc[TM];
#pragma unroll
        for (int m = 0; m < TM; ++m) acc[m] = 0.f;

        for (int k = 0; k < F; k += 4) {
            float4 xv[TM];
#pragma unroll
            for (int m = 0; m < TM; ++m) xv[m] = sx4[(m * F + k) >> 2];
#pragma unroll
            for (int kk = 0; kk < 4; ++kk) {
                float wv = sW[(k + kk) * 128 + f];
#pragma unroll
                for (int m = 0; m < TM; ++m) {
                    float xe = (kk == 0) ? xv[m].x : (kk == 1) ? xv[m].y
                             : (kk == 2) ? xv[m].z : xv[m].w;
                    acc[m] = fmaf(xe, wv, acc[m]);
                }
            }
        }

#pragma unroll
        for (int m = 0; m < TM; ++m) {
            int n = n0 + m;
            if (n < NN) h[(size_t)n * 128 + f] = acc[m];
            float vs = acc[m] * as;
            float vd = acc[m] * ad;
#pragma unroll
            for (int o = 16; o > 0; o >>= 1) {
                vs += __shfl_down_sync(0xffffffffu, vs, o);
                vd += __shfl_down_sync(0xffffffffu, vd, o);
            }
            if (lane == 0 && n < NN) {
                alS[n * 4 + head] = vs;
                alD[n * 4 + head] = vd;
            }
        }
    }
}

// ---------------- fused attention + aggregate + head-mean + bias ----------------
// warp per dst node; lane = head*8 + pos (pos indexes 8 float4 = 32 channels)
__global__ void gather_k(const int* __restrict__ rowptr,
                         const int* __restrict__ csr_src,
                         const float4* __restrict__ alS4,  // [N] (4 heads)
                         const float4* __restrict__ alD4,  // [N]
                         const float4* __restrict__ h,     // [N,32] float4
                         const float4* __restrict__ bias4, // [8]
                         float4* __restrict__ out4)        // [N,8] float4
{
    int gid = blockIdx.x * blockDim.x + threadIdx.x;
    int n = gid >> 5;
    if (n >= NN) return;
    const int lane = gid & 31;
    const int head = lane >> 3;

    const int beg = rowptr[n];
    const int end = rowptr[n + 1];
    const float4 ad4 = alD4[n];   // broadcast load

    // pass 1: softmax denominator, edges distributed across lanes, all 4 heads
    float4 den4 = make_float4(0.f, 0.f, 0.f, 0.f);
    for (int k = beg + lane; k < end; k += 32) {
        int s = csr_src[k];
        float4 a = alS4[s];
        den4.x += __expf(leaky(a.x + ad4.x));
        den4.y += __expf(leaky(a.y + ad4.y));
        den4.z += __expf(leaky(a.z + ad4.z));
        den4.w += __expf(leaky(a.w + ad4.w));
    }
#pragma unroll
    for (int off = 16; off > 0; off >>= 1) {
        den4.x += __shfl_xor_sync(0xffffffffu, den4.x, off);
        den4.y += __shfl_xor_sync(0xffffffffu, den4.y, off);
        den4.z += __shfl_xor_sync(0xffffffffu, den4.z, off);
        den4.w += __shfl_xor_sync(0xffffffffu, den4.w, off);
    }
    const float den = (head == 0) ? den4.x : (head == 1) ? den4.y
                    : (head == 2) ? den4.z : den4.w;
    const float ad = (head == 0) ? ad4.x : (head == 1) ? ad4.y
                   : (head == 2) ? ad4.z : ad4.w;
    const float wsc = 0.25f / den;  // deg==0 -> loop below empty, wsc unused

    // pass 2: weighted aggregation with src-id prefetch
    const float* alS = reinterpret_cast<const float*>(alS4);
    float4 acc = make_float4(0.f, 0.f, 0.f, 0.f);
    int k = beg;
    int s = (k < end) ? csr_src[k] : 0;
    while (k < end) {
        int s_next = (k + 1 < end) ? csr_src[k + 1] : 0;
        float e = leaky(alS[s * 4 + head] + ad);
        float w = __expf(e) * wsc;
        float4 hv = h[(size_t)s * 32 + lane];
        acc.x = fmaf(w, hv.x, acc.x);
        acc.y = fmaf(w, hv.y, acc.y);
        acc.z = fmaf(w, hv.z, acc.z);
        acc.w = fmaf(w, hv.w, acc.w);
        s = s_next;
        ++k;
    }

    // head mean: sum the 4 heads (lanes differing in bits 3,4)
#pragma unroll
    for (int off = 8; off <= 16; off <<= 1) {
        acc.x += __shfl_xor_sync(0xffffffffu, acc.x, off);
        acc.y += __shfl_xor_sync(0xffffffffu, acc.y, off);
        acc.z += __shfl_xor_sync(0xffffffffu, acc.z, off);
        acc.w += __shfl_xor_sync(0xffffffffu, acc.w, off);
    }

    if (lane < 8) {
        float4 b = bias4[lane];
        float4 r;
        r.x = acc.x + b.x; r.y = acc.y + b.y;
        r.z = acc.z + b.z; r.w = acc.w + b.w;
        out4[(size_t)n * 8 + lane] = r;
    }
}

// ---------------- BN stats over y ----------------
__global__ void bn_stats_k(const float* __restrict__ y,
                           float* __restrict__ bnsum, float* __restrict__ bnsq)
{
    __shared__ float s1[1024];
    __shared__ float s2[1024];
    int tid = threadIdx.x;
    int c = tid & 31;
    int n = blockIdx.x * 32 + (tid >> 5);
    float val = (n < NN) ? y[(size_t)n * 32 + c] : 0.f;
    s1[tid] = val;
    s2[tid] = val * val;
    __syncthreads();
    for (int st = 512; st >= 32; st >>= 1) {
        if (tid < st) { s1[tid] += s1[tid + st]; s2[tid] += s2[tid + st]; }
        __syncthreads();
    }
    if (tid < 32) {
        atomicAdd(&bnsum[tid * 32], s1[tid]);
        atomicAdd(&bnsq[tid * 32], s2[tid]);
    }
}

__global__ void bn_params_k(const float* __restrict__ bnsum, const float* __restrict__ bnsq,
                            const float* __restrict__ g, const float* __restrict__ be,
                            float* __restrict__ scale, float* __restrict__ shift)
{
    int c = threadIdx.x;
    if (c >= 32) return;
    float mu = bnsum[c * 32] * (1.f / NN);
    float var = bnsq[c * 32] * (1.f / NN) - mu * mu;
    float sc = g[c] * rsqrtf(var + BN_EPS);
    scale[c] = sc;
    shift[c] = be[c] - mu * sc;
}

// ---------------- host ----------------
extern "C" void kernel_launch(void* const* d_in, const int* in_sizes, int n_in,
                              void* d_out, int out_size)
{
    const float* x   = (const float*)d_in[0];
    const int*   ei  = (const int*)  d_in[1];
    const float* ea  = (const float*)d_in[2];
    const float* W[3]   = {(const float*)d_in[3],  (const float*)d_in[9],  (const float*)d_in[15]};
    const float* aS[3]  = {(const float*)d_in[4],  (const float*)d_in[10], (const float*)d_in[16]};
    const float* aD[3]  = {(const float*)d_in[5],  (const float*)d_in[11], (const float*)d_in[17]};
    const float* bia[3] = {(const float*)d_in[6],  (const float*)d_in[12], (const float*)d_in[18]};
    const float* gam[2] = {(const float*)d_in[7],  (const float*)d_in[13]};
    const float* bet[2] = {(const float*)d_in[8],  (const float*)d_in[14]};
    const int* src = ei;
    const int* dst = ei + NE;

    void *ph, *py, *pals, *pald, *pdeg, *prow, *pcur, *pcsr, *pbn, *psc, *psh;
    cudaGetSymbolAddress(&ph, g_h);
    cudaGetSymbolAddress(&py, g_y);
    cudaGetSymbolAddress(&pals, g_alS);
    cudaGetSymbolAddress(&pald, g_alD);
    cudaGetSymbolAddress(&pdeg, g_deg);
    cudaGetSymbolAddress(&prow, g_rowptr);
    cudaGetSymbolAddress(&pcur, g_cursor);
    cudaGetSymbolAddress(&pcsr, g_csr_src);
    cudaGetSymbolAddress(&pbn, g_bn);
    cudaGetSymbolAddress(&psc, g_scale);
    cudaGetSymbolAddress(&psh, g_shift);

    const int SM128 = 128 * 128 * 4 + NG * TM * 128 * 4;  // 81920
    const int SM32  = 32 * 128 * 4  + NG * TM * 32 * 4;   // 20480
    cudaFuncSetAttribute(gemm_al<128>, cudaFuncAttributeMaxDynamicSharedMemorySize, SM128);
    cudaFuncSetAttribute(gemm_al<32>,  cudaFuncAttributeMaxDynamicSharedMemorySize, SM32);

    const int GEMM_BLOCKS = (NN + 127) / 128;     // 782
    const int EB = (NE + 255) / 256;              // 6250
    const int GB = (NN * 32 + 255) / 256;         // 12500
    const int BB = (NN + 31) / 32;                // 3125

    // ---- CSR build (once; reused by all 3 layers) ----
    cudaMemsetAsync(pdeg, 0, NN * sizeof(int));
    hist_k<<<EB, 256>>>(dst, (int*)pdeg);
    scan_k<<<1, 1024>>>((const int*)pdeg, (int*)prow, (int*)pcur);
    scatter_build_k<<<EB, 256>>>(src, dst, (int*)pcur, (int*)pcsr);

    for (int L = 0; L < 3; ++L) {
        if (L == 0) {
            gemm_al<128><<<GEMM_BLOCKS, 512, SM128>>>(
                x, W[0], aS[0], aD[0], nullptr, nullptr,
                (float*)ph, (float*)pals, (float*)pald, 0);
        } else {
            gemm_al<32><<<GEMM_BLOCKS, 512, SM32>>>(
                (const float*)py, W[L], aS[L], aD[L],
                (const float*)psc, (const float*)psh,
                (float*)ph, (float*)pals, (float*)pald, 1);
        }

        float* dest = (L < 2) ? (float*)py : (float*)d_out;
        gather_k<<<GB, 256>>>((const int*)prow, (const int*)pcsr,
                              (const float4*)pals, (const float4*)pald,
                              (const float4*)ph, (const float4*)bia[L],
                              (float4*)dest);

        if (L < 2) {
            cudaMemsetAsync(pbn, 0, 2 * 32 * 32 * sizeof(float));
            bn_stats_k<<<BB, 1024>>>((const float*)py, (float*)pbn, (float*)pbn + 1024);
            bn_params_k<<<1, 32>>>((const float*)pbn, (const float*)pbn + 1024,
                                   gam[L], bet[L], (float*)psc, (float*)psh);
        }
    }

    cudaMemcpyAsync((float*)d_out + (size_t)NN * 32, ea,
                    (size_t)NE * 8 * sizeof(float), cudaMemcpyDeviceToDevice);
}

// round 6
// speedup vs baseline: 1.8123x; 1.8123x over previous
#include <cuda_runtime.h>
#include <cstdint>

#define NN 100000
#define NE 1600000
#define NEG_SLOPE 0.2f
#define BN_EPS 1e-5f

// ---------------- scratch (static __device__, no allocation) ----------------
__device__ __align__(16) float g_h[(size_t)NN * 128];   // GEMM output [N,4,32]
__device__ __align__(16) float g_y[(size_t)NN * 32];    // per-layer node features
__device__ __align__(16) float g_alS[(size_t)NN * 4];
__device__ __align__(16) float g_alD[(size_t)NN * 4];
__device__ int g_deg[NN];
__device__ int g_rowptr[NN + 1];
__device__ int g_cursor[NN];
__device__ int g_csr_src[NE];
__device__ float g_bn[2 * 32 * 32];                     // strided sums / sumsq
__device__ float g_scale[32];
__device__ float g_shift[32];

__device__ __forceinline__ float leaky(float e) {
    return e >= 0.f ? e : NEG_SLOPE * e;
}

// ---------------- CSR build ----------------
__global__ void hist_k(const int* __restrict__ dst, int* __restrict__ deg) {
    int i = blockIdx.x * blockDim.x + threadIdx.x;
    if (i < NE) atomicAdd(&deg[dst[i]], 1);
}

// single block, 1024 threads: chunked exclusive scan of deg -> rowptr, cursor
__global__ void scan_k(const int* __restrict__ deg, int* __restrict__ rowptr,
                       int* __restrict__ cursor) {
    __shared__ int sc[1024];
    const int tid = threadIdx.x;
    const int CH = (NN + 1023) / 1024;  // 98
    const int base = tid * CH;
    int s = 0;
    for (int i = 0; i < CH; ++i) {
        int idx = base + i;
        if (idx < NN) s += deg[idx];
    }
    sc[tid] = s;
    __syncthreads();
    for (int off = 1; off < 1024; off <<= 1) {
        int v = (tid >= off) ? sc[tid - off] : 0;
        __syncthreads();
        sc[tid] += v;
        __syncthreads();
    }
    int run = sc[tid] - s;
    for (int i = 0; i < CH; ++i) {
        int idx = base + i;
        if (idx < NN) {
            rowptr[idx] = run;
            cursor[idx] = run;
            run += deg[idx];
        }
    }
    if (tid == 1023) rowptr[NN] = sc[1023];
}

__global__ void scatter_build_k(const int* __restrict__ src, const int* __restrict__ dst,
                                int* __restrict__ cursor, int* __restrict__ csr_src) {
    int i = blockIdx.x * blockDim.x + threadIdx.x;
    if (i >= NE) return;
    int p = atomicAdd(&cursor[dst[i]], 1);
    csr_src[p] = src[i];
}

// ---------------- GEMM + attention logits (fused prev-layer BN+ReLU) ----------------
// 256 threads = 2 groups x 128; 64 nodes/block; NO launch_bounds (no reg cap / no spills)
#define TM 8
#define NG 2
template<int F>
__global__ void gemm_al(const float* __restrict__ x,     // [N,F]
                        const float* __restrict__ W,     // [F,128]
                        const float* __restrict__ aS,    // [128]
                        const float* __restrict__ aD,    // [128]
                        const float* __restrict__ scale, // [F] or null
                        const float* __restrict__ shift, // [F] or null
                        float* __restrict__ h,           // [N,128]
                        float* __restrict__ alS,         // [N,4]
                        float* __restrict__ alD,         // [N,4]
                        int useBN)
{
    extern __shared__ float sm[];
    float* sW = sm;                               // F*128
    const int tid = threadIdx.x;
    const int f = tid & 127;
    const int grp = tid >> 7;
    float* sx = sm + F * 128 + grp * TM * F;      // per-group staging
    const int lane = tid & 31;
    const int head = f >> 5;

    for (int i = tid; i < F * 128; i += 256) sW[i] = W[i];
    const float as = aS[f];
    const float ad = aD[f];
    __syncthreads();

    const int nodeBase = blockIdx.x * 64;
    const float4* sx4 = reinterpret_cast<const float4*>(sx);

    for (int t = 0; t < 4; ++t) {
        int n0 = nodeBase + (t * NG + grp) * TM;
        __syncthreads();
        for (int i = f; i < TM * F; i += 128) {
            int m = i / F, k = i - m * F;
            int n = n0 + m;
            float v = 0.f;
            if (n < NN) {
                v = x[(size_t)n * F + k];
                if (useBN) v = fmaxf(fmaf(v, scale[k], shift[k]), 0.f);
            }
            sx[i] = v;
        }
        __syncthreads();

        float acc[TM];
#pragma unroll
        for (int m = 0; m < TM; ++m) acc[m] = 0.f;

        for (int k = 0; k < F; k += 4) {
            float4 xv[TM];
#pragma unroll
            for (int m = 0; m < TM; ++m) xv[m] = sx4[(m * F + k) >> 2];
#pragma unroll
            for (int kk = 0; kk < 4; ++kk) {
                float wv = sW[(k + kk) * 128 + f];
#pragma unroll
                for (int m = 0; m < TM; ++m) {
                    float xe = (kk == 0) ? xv[m].x : (kk == 1) ? xv[m].y
                             : (kk == 2) ? xv[m].z : xv[m].w;
                    acc[m] = fmaf(xe, wv, acc[m]);
                }
            }
        }

#pragma unroll
        for (int m = 0; m < TM; ++m) {
            int n = n0 + m;
            if (n < NN) h[(size_t)n * 128 + f] = acc[m];
            float vs = acc[m] * as;
            float vd = acc[m] * ad;
#pragma unroll
            for (int o = 16; o > 0; o >>= 1) {
                vs += __shfl_down_sync(0xffffffffu, vs, o);
                vd += __shfl_down_sync(0xffffffffu, vd, o);
            }
            if (lane == 0 && n < NN) {
                alS[n * 4 + head] = vs;
                alD[n * 4 + head] = vd;
            }
        }
    }
}

// ---------------- fused attention + aggregate + head-mean + bias ----------------
// warp per dst node; lane = head*8 + pos (pos indexes 8 float4 = 32 channels)
__global__ void gather_k(const int* __restrict__ rowptr,
                         const int* __restrict__ csr_src,
                         const float4* __restrict__ alS4,  // [N] (4 heads)
                         const float4* __restrict__ alD4,  // [N]
                         const float4* __restrict__ h,     // [N,32] float4
                         const float4* __restrict__ bias4, // [8]
                         float4* __restrict__ out4)        // [N,8] float4
{
    int gid = blockIdx.x * blockDim.x + threadIdx.x;
    int n = gid >> 5;
    if (n >= NN) return;
    const int lane = gid & 31;
    const int head = lane >> 3;

    const int beg = rowptr[n];
    const int end = rowptr[n + 1];
    const float4 ad4 = alD4[n];   // broadcast load

    // pass 1: softmax denominator, edges distributed across lanes, all 4 heads
    float4 den4 = make_float4(0.f, 0.f, 0.f, 0.f);
    for (int k = beg + lane; k < end; k += 32) {
        int s = csr_src[k];
        float4 a = alS4[s];
        den4.x += __expf(leaky(a.x + ad4.x));
        den4.y += __expf(leaky(a.y + ad4.y));
        den4.z += __expf(leaky(a.z + ad4.z));
        den4.w += __expf(leaky(a.w + ad4.w));
    }
#pragma unroll
    for (int off = 16; off > 0; off >>= 1) {
        den4.x += __shfl_xor_sync(0xffffffffu, den4.x, off);
        den4.y += __shfl_xor_sync(0xffffffffu, den4.y, off);
        den4.z += __shfl_xor_sync(0xffffffffu, den4.z, off);
        den4.w += __shfl_xor_sync(0xffffffffu, den4.w, off);
    }
    const float den = (head == 0) ? den4.x : (head == 1) ? den4.y
                    : (head == 2) ? den4.z : den4.w;
    const float ad = (head == 0) ? ad4.x : (head == 1) ? ad4.y
                   : (head == 2) ? ad4.z : ad4.w;
    const float wsc = 0.25f / den;  // deg==0 -> loop below empty, wsc unused

    // pass 2: weighted aggregation with src-id prefetch
    const float* alS = reinterpret_cast<const float*>(alS4);
    float4 acc = make_float4(0.f, 0.f, 0.f, 0.f);
    int k = beg;
    int s = (k < end) ? csr_src[k] : 0;
    while (k < end) {
        int s_next = (k + 1 < end) ? csr_src[k + 1] : 0;
        float e = leaky(alS[s * 4 + head] + ad);
        float w = __expf(e) * wsc;
        float4 hv = h[(size_t)s * 32 + lane];
        acc.x = fmaf(w, hv.x, acc.x);
        acc.y = fmaf(w, hv.y, acc.y);
        acc.z = fmaf(w, hv.z, acc.z);
        acc.w = fmaf(w, hv.w, acc.w);
        s = s_next;
        ++k;
    }

    // head mean: sum the 4 heads (lanes differing in bits 3,4)
#pragma unroll
    for (int off = 8; off <= 16; off <<= 1) {
        acc.x += __shfl_xor_sync(0xffffffffu, acc.x, off);
        acc.y += __shfl_xor_sync(0xffffffffu, acc.y, off);
        acc.z += __shfl_xor_sync(0xffffffffu, acc.z, off);
        acc.w += __shfl_xor_sync(0xffffffffu, acc.w, off);
    }

    if (lane < 8) {
        float4 b = bias4[lane];
        float4 r;
        r.x = acc.x + b.x; r.y = acc.y + b.y;
        r.z = acc.z + b.z; r.w = acc.w + b.w;
        out4[(size_t)n * 8 + lane] = r;
    }
}

// ---------------- BN stats over y ----------------
__global__ void bn_stats_k(const float* __restrict__ y,
                           float* __restrict__ bnsum, float* __restrict__ bnsq)
{
    __shared__ float s1[1024];
    __shared__ float s2[1024];
    int tid = threadIdx.x;
    int c = tid & 31;
    int n = blockIdx.x * 32 + (tid >> 5);
    float val = (n < NN) ? y[(size_t)n * 32 + c] : 0.f;
    s1[tid] = val;
    s2[tid] = val * val;
    __syncthreads();
    for (int st = 512; st >= 32; st >>= 1) {
        if (tid < st) { s1[tid] += s1[tid + st]; s2[tid] += s2[tid + st]; }
        __syncthreads();
    }
    if (tid < 32) {
        atomicAdd(&bnsum[tid * 32], s1[tid]);
        atomicAdd(&bnsq[tid * 32], s2[tid]);
    }
}

__global__ void bn_params_k(const float* __restrict__ bnsum, const float* __restrict__ bnsq,
                            const float* __restrict__ g, const float* __restrict__ be,
                            float* __restrict__ scale, float* __restrict__ shift)
{
    int c = threadIdx.x;
    if (c >= 32) return;
    float mu = bnsum[c * 32] * (1.f / NN);
    float var = bnsq[c * 32] * (1.f / NN) - mu * mu;
    float sc = g[c] * rsqrtf(var + BN_EPS);
    scale[c] = sc;
    shift[c] = be[c] - mu * sc;
}

// ---------------- host ----------------
extern "C" void kernel_launch(void* const* d_in, const int* in_sizes, int n_in,
                              void* d_out, int out_size)
{
    const float* x   = (const float*)d_in[0];
    const int*   ei  = (const int*)  d_in[1];
    const float* ea  = (const float*)d_in[2];
    const float* W[3]   = {(const float*)d_in[3],  (const float*)d_in[9],  (const float*)d_in[15]};
    const float* aS[3]  = {(const float*)d_in[4],  (const float*)d_in[10], (const float*)d_in[16]};
    const float* aD[3]  = {(const float*)d_in[5],  (const float*)d_in[11], (const float*)d_in[17]};
    const float* bia[3] = {(const float*)d_in[6],  (const float*)d_in[12], (const float*)d_in[18]};
    const float* gam[2] = {(const float*)d_in[7],  (const float*)d_in[13]};
    const float* bet[2] = {(const float*)d_in[8],  (const float*)d_in[14]};
    const int* src = ei;
    const int* dst = ei + NE;

    void *ph, *py, *pals, *pald, *pdeg, *prow, *pcur, *pcsr, *pbn, *psc, *psh;
    cudaGetSymbolAddress(&ph, g_h);
    cudaGetSymbolAddress(&py, g_y);
    cudaGetSymbolAddress(&pals, g_alS);
    cudaGetSymbolAddress(&pald, g_alD);
    cudaGetSymbolAddress(&pdeg, g_deg);
    cudaGetSymbolAddress(&prow, g_rowptr);
    cudaGetSymbolAddress(&pcur, g_cursor);
    cudaGetSymbolAddress(&pcsr, g_csr_src);
    cudaGetSymbolAddress(&pbn, g_bn);
    cudaGetSymbolAddress(&psc, g_scale);
    cudaGetSymbolAddress(&psh, g_shift);

    const int SM128 = 128 * 128 * 4 + NG * TM * 128 * 4;  // 73728
    const int SM32  = 32 * 128 * 4  + NG * TM * 32 * 4;   // 18432
    cudaFuncSetAttribute(gemm_al<128>, cudaFuncAttributeMaxDynamicSharedMemorySize, SM128);
    cudaFuncSetAttribute(gemm_al<32>,  cudaFuncAttributeMaxDynamicSharedMemorySize, SM32);

    const int GEMM_BLOCKS = (NN + 63) / 64;       // 1563
    const int EB = (NE + 255) / 256;              // 6250
    const int GB = (NN * 32 + 255) / 256;         // 12500
    const int BB = (NN + 31) / 32;                // 3125

    // ---- CSR build (once; reused by all 3 layers) ----
    cudaMemsetAsync(pdeg, 0, NN * sizeof(int));
    hist_k<<<EB, 256>>>(dst, (int*)pdeg);
    scan_k<<<1, 1024>>>((const int*)pdeg, (int*)prow, (int*)pcur);
    scatter_build_k<<<EB, 256>>>(src, dst, (int*)pcur, (int*)pcsr);

    for (int L = 0; L < 3; ++L) {
        if (L == 0) {
            gemm_al<128><<<GEMM_BLOCKS, 256, SM128>>>(
                x, W[0], aS[0], aD[0], nullptr, nullptr,
                (float*)ph, (float*)pals, (float*)pald, 0);
        } else {
            gemm_al<32><<<GEMM_BLOCKS, 256, SM32>>>(
                (const float*)py, W[L], aS[L], aD[L],
                (const float*)psc, (const float*)psh,
                (float*)ph, (float*)pals, (float*)pald, 1);
        }

        float* dest = (L < 2) ? (float*)py : (float*)d_out;
        gather_k<<<GB, 256>>>((const int*)prow, (const int*)pcsr,
                              (const float4*)pals, (const float4*)pald,
                              (const float4*)ph, (const float4*)bia[L],
                              (float4*)dest);

        if (L < 2) {
            cudaMemsetAsync(pbn, 0, 2 * 32 * 32 * sizeof(float));
            bn_stats_k<<<BB, 1024>>>((const float*)py, (float*)pbn, (float*)pbn + 1024);
            bn_params_k<<<1, 32>>>((const float*)pbn, (const float*)pbn + 1024,
                                   gam[L], bet[L], (float*)psc, (float*)psh);
        }
    }

    cudaMemcpyAsync((float*)d_out + (size_t)NN * 32, ea,
                    (size_t)NE * 8 * sizeof(float), cudaMemcpyDeviceToDevice);
}

// round 8
// speedup vs baseline: 1.8477x; 1.0196x over previous
#include <cuda_runtime.h>
#include <cstdint>

#define NN 100000
#define NE 1600000
#define NEG_SLOPE 0.2f
#define BN_EPS 1e-5f

// ---------------- scratch (static __device__, no allocation) ----------------
__device__ __align__(16) float g_h[(size_t)NN * 128];   // GEMM output [N,4,32]
__device__ __align__(16) float g_y[(size_t)NN * 32];    // per-layer node features
__device__ __align__(16) float g_alS[(size_t)NN * 4];
__device__ __align__(16) float g_alD[(size_t)NN * 4];
__device__ int g_deg[NN];
__device__ int g_rowptr[NN + 1];
__device__ int g_cursor[NN];
__device__ int g_csr_src[NE];
__device__ float g_bn[2 * 32 * 32];                     // strided sums / sumsq
__device__ float g_scale[32];
__device__ float g_shift[32];

__device__ __forceinline__ float leaky(float e) {
    return e >= 0.f ? e : NEG_SLOPE * e;
}

// ---------------- CSR build ----------------
__global__ void hist_k(const int* __restrict__ dst, int* __restrict__ deg) {
    int i = blockIdx.x * blockDim.x + threadIdx.x;
    if (i < NE) atomicAdd(&deg[dst[i]], 1);
}

// single block, 1024 threads: chunked exclusive scan of deg -> rowptr, cursor
__global__ void scan_k(const int* __restrict__ deg, int* __restrict__ rowptr,
                       int* __restrict__ cursor) {
    __shared__ int sc[1024];
    const int tid = threadIdx.x;
    const int CH = (NN + 1023) / 1024;  // 98
    const int base = tid * CH;
    int s = 0;
    for (int i = 0; i < CH; ++i) {
        int idx = base + i;
        if (idx < NN) s += deg[idx];
    }
    sc[tid] = s;
    __syncthreads();
    for (int off = 1; off < 1024; off <<= 1) {
        int v = (tid >= off) ? sc[tid - off] : 0;
        __syncthreads();
        sc[tid] += v;
        __syncthreads();
    }
    int run = sc[tid] - s;
    for (int i = 0; i < CH; ++i) {
        int idx = base + i;
        if (idx < NN) {
            rowptr[idx] = run;
            cursor[idx] = run;
            run += deg[idx];
        }
    }
    if (tid == 1023) rowptr[NN] = sc[1023];
}

__global__ void scatter_build_k(const int* __restrict__ src, const int* __restrict__ dst,
                                int* __restrict__ cursor, int* __restrict__ csr_src) {
    int i = blockIdx.x * blockDim.x + threadIdx.x;
    if (i >= NE) return;
    int p = atomicAdd(&cursor[dst[i]], 1);
    csr_src[p] = src[i];
}

// ---------------- GEMM + attention logits (fused prev-layer BN+ReLU) ----------------
// 256 threads = 4 groups x 64. Thread computes 2 columns (c, c+64) x 8 nodes.
// W stored transposed in smem (pad stride F+4) so W reads are LDS.128.
#define TM 8
#define NGRP 4
template<int F>
__global__ void gemm_al(const float* __restrict__ x,     // [N,F]
                        const float* __restrict__ W,     // [F,128] (k-major)
                        const float* __restrict__ aS,    // [128]
                        const float* __restrict__ aD,    // [128]
                        const float* __restrict__ scale, // [F] or null
                        const float* __restrict__ shift, // [F] or null
                        float* __restrict__ h,           // [N,128]
                        float* __restrict__ alS,         // [N,4]
                        float* __restrict__ alD,         // [N,4]
                        int useBN)
{
    constexpr int FP = F + 4;                      // padded k-stride
    extern __shared__ float sm[];
    float* sWT = sm;                               // [128][FP] transposed W
    const int tid = threadIdx.x;
    const int c   = tid & 63;                      // column (and c+64)
    const int grp = tid >> 6;
    float* sx = sm + 128 * FP + grp * TM * F;      // per-group staging [TM][F]
    const int lane = tid & 31;
    const int h0 = c >> 5;                         // head of col c (0 or 1)

    // load W transposed: sWT[f*FP + k] = W[k*128 + f]
    for (int i = tid; i < F * 128; i += 256) {
        int k = i >> 7, f = i & 127;
        sWT[f * FP + k] = W[i];
    }
    const float as0 = aS[c],      ad0 = aD[c];
    const float as1 = aS[c + 64], ad1 = aD[c + 64];
    __syncthreads();

    const int nodeBase = blockIdx.x * 64;
    const float4* sx4  = reinterpret_cast<const float4*>(sx);
    const float4* sWT4 = reinterpret_cast<const float4*>(sWT);
    const int w0base = (c * FP) >> 2;
    const int w1base = ((c + 64) * FP) >> 2;

    for (int t = 0; t < 2; ++t) {
        int n0 = nodeBase + (t * NGRP + grp) * TM;
        __syncthreads();
        for (int i = c; i < TM * F; i += 64) {
            int m = i / F, k = i - m * F;
            int n = n0 + m;
            float v = 0.f;
            if (n < NN) {
                v = x[(size_t)n * F + k];
                if (useBN) v = fmaxf(fmaf(v, scale[k], shift[k]), 0.f);
            }
            sx[i] = v;
        }
        __syncthreads();

        float acc0[TM], acc1[TM];
#pragma unroll
        for (int m = 0; m < TM; ++m) { acc0[m] = 0.f; acc1[m] = 0.f; }

        for (int k = 0; k < F; k += 4) {
            float4 w0 = sWT4[w0base + (k >> 2)];
            float4 w1 = sWT4[w1base + (k >> 2)];
            float4 xv[TM];
#pragma unroll
            for (int m = 0; m < TM; ++m) xv[m] = sx4[(m * F + k) >> 2];
#pragma unroll
            for (int m = 0; m < TM; ++m) {
                acc0[m] = fmaf(xv[m].x, w0.x, acc0[m]);
                acc0[m] = fmaf(xv[m].y, w0.y, acc0[m]);
                acc0[m] = fmaf(xv[m].z, w0.z, acc0[m]);
                acc0[m] = fmaf(xv[m].w, w0.w, acc0[m]);
                acc1[m] = fmaf(xv[m].x, w1.x, acc1[m]);
                acc1[m] = fmaf(xv[m].y, w1.y, acc1[m]);
                acc1[m] = fmaf(xv[m].z, w1.z, acc1[m]);
                acc1[m] = fmaf(xv[m].w, w1.w, acc1[m]);
            }
        }

#pragma unroll
        for (int m = 0; m < TM; ++m) {
            int n = n0 + m;
            if (n < NN) {
                h[(size_t)n * 128 + c]      = acc0[m];
                h[(size_t)n * 128 + c + 64] = acc1[m];
            }
            float vs0 = acc0[m] * as0, vd0 = acc0[m] * ad0;
            float vs1 = acc1[m] * as1, vd1 = acc1[m] * ad1;
#pragma unroll
            for (int o = 16; o > 0; o >>= 1) {
                vs0 += __shfl_down_sync(0xffffffffu, vs0, o);
                vd0 += __shfl_down_sync(0xffffffffu, vd0, o);
                vs1 += __shfl_down_sync(0xffffffffu, vs1, o);
                vd1 += __shfl_down_sync(0xffffffffu, vd1, o);
            }
            if (lane == 0 && n < NN) {
                alS[n * 4 + h0]     = vs0;
                alD[n * 4 + h0]     = vd0;
                alS[n * 4 + h0 + 2] = vs1;
                alD[n * 4 + h0 + 2] = vd1;
            }
        }
    }
}

// ---------------- fused attention + aggregate + head-mean + bias ----------------
// warp per dst node; lane = head*8 + pos (pos indexes 8 float4 = 32 channels)
__global__ void gather_k(const int* __restrict__ rowptr,
                         const int* __restrict__ csr_src,
                         const float4* __restrict__ alS4,  // [N] (4 heads)
                         const float4* __restrict__ alD4,  // [N]
                         const float4* __restrict__ h,     // [N,32] float4
                         const float4* __restrict__ bias4, // [8]
                         float4* __restrict__ out4)        // [N,8] float4
{
    int gid = blockIdx.x * blockDim.x + threadIdx.x;
    int n = gid >> 5;
    if (n >= NN) return;
    const int lane = gid & 31;
    const int head = lane >> 3;

    const int beg = rowptr[n];
    const int end = rowptr[n + 1];
    const float4 ad4 = alD4[n];   // broadcast load

    // pass 1: softmax denominator, edges distributed across lanes, all 4 heads
    float4 den4 = make_float4(0.f, 0.f, 0.f, 0.f);
    for (int k = beg + lane; k < end; k += 32) {
        int s = csr_src[k];
        float4 a = alS4[s];
        den4.x += __expf(leaky(a.x + ad4.x));
        den4.y += __expf(leaky(a.y + ad4.y));
        den4.z += __expf(leaky(a.z + ad4.z));
        den4.w += __expf(leaky(a.w + ad4.w));
    }
#pragma unroll
    for (int off = 16; off > 0; off >>= 1) {
        den4.x += __shfl_xor_sync(0xffffffffu, den4.x, off);
        den4.y += __shfl_xor_sync(0xffffffffu, den4.y, off);
        den4.z += __shfl_xor_sync(0xffffffffu, den4.z, off);
        den4.w += __shfl_xor_sync(0xffffffffu, den4.w, off);
    }
    const float den = (head == 0) ? den4.x : (head == 1) ? den4.y
                    : (head == 2) ? den4.z : den4.w;
    const float ad = (head == 0) ? ad4.x : (head == 1) ? ad4.y
                   : (head == 2) ? ad4.z : ad4.w;
    const float wsc = 0.25f / den;  // deg==0 -> loop below empty, wsc unused

    // pass 2: weighted aggregation with src-id prefetch
    const float* alS = reinterpret_cast<const float*>(alS4);
    float4 acc = make_float4(0.f, 0.f, 0.f, 0.f);
    int k = beg;
    int s = (k < end) ? csr_src[k] : 0;
    while (k < end) {
        int s_next = (k + 1 < end) ? csr_src[k + 1] : 0;
        float e = leaky(alS[s * 4 + head] + ad);
        float w = __expf(e) * wsc;
        float4 hv = h[(size_t)s * 32 + lane];
        acc.x = fmaf(w, hv.x, acc.x);
        acc.y = fmaf(w, hv.y, acc.y);
        acc.z = fmaf(w, hv.z, acc.z);
        acc.w = fmaf(w, hv.w, acc.w);
        s = s_next;
        ++k;
    }

    // head mean: sum the 4 heads (lanes differing in bits 3,4)
#pragma unroll
    for (int off = 8; off <= 16; off <<= 1) {
        acc.x += __shfl_xor_sync(0xffffffffu, acc.x, off);
        acc.y += __shfl_xor_sync(0xffffffffu, acc.y, off);
        acc.z += __shfl_xor_sync(0xffffffffu, acc.z, off);
        acc.w += __shfl_xor_sync(0xffffffffu, acc.w, off);
    }

    if (lane < 8) {
        float4 b = bias4[lane];
        float4 r;
        r.x = acc.x + b.x; r.y = acc.y + b.y;
        r.z = acc.z + b.z; r.w = acc.w + b.w;
        out4[(size_t)n * 8 + lane] = r;
    }
}

// ---------------- BN stats over y ----------------
__global__ void bn_stats_k(const float* __restrict__ y,
                           float* __restrict__ bnsum, float* __restrict__ bnsq)
{
    __shared__ float s1[1024];
    __shared__ float s2[1024];
    int tid = threadIdx.x;
    int c = tid & 31;
    int n = blockIdx.x * 32 + (tid >> 5);
    float val = (n < NN) ? y[(size_t)n * 32 + c] : 0.f;
    s1[tid] = val;
    s2[tid] = val * val;
    __syncthreads();
    for (int st = 512; st >= 32; st >>= 1) {
        if (tid < st) { s1[tid] += s1[tid + st]; s2[tid] += s2[tid + st]; }
        __syncthreads();
    }
    if (tid < 32) {
        atomicAdd(&bnsum[tid * 32], s1[tid]);
        atomicAdd(&bnsq[tid * 32], s2[tid]);
    }
}

__global__ void bn_params_k(const float* __restrict__ bnsum, const float* __restrict__ bnsq,
                            const float* __restrict__ g, const float* __restrict__ be,
                            float* __restrict__ scale, float* __restrict__ shift)
{
    int c = threadIdx.x;
    if (c >= 32) return;
    float mu = bnsum[c * 32] * (1.f / NN);
    float var = bnsq[c * 32] * (1.f / NN) - mu * mu;
    float sc = g[c] * rsqrtf(var + BN_EPS);
    scale[c] = sc;
    shift[c] = be[c] - mu * sc;
}

// ---------------- host ----------------
extern "C" void kernel_launch(void* const* d_in, const int* in_sizes, int n_in,
                              void* d_out, int out_size)
{
    const float* x   = (const float*)d_in[0];
    const int*   ei  = (const int*)  d_in[1];
    const float* ea  = (const float*)d_in[2];
    const float* W[3]   = {(const float*)d_in[3],  (const float*)d_in[9],  (const float*)d_in[15]};
    const float* aS[3]  = {(const float*)d_in[4],  (const float*)d_in[10], (const float*)d_in[16]};
    const float* aD[3]  = {(const float*)d_in[5],  (const float*)d_in[11], (const float*)d_in[17]};
    const float* bia[3] = {(const float*)d_in[6],  (const float*)d_in[12], (const float*)d_in[18]};
    const float* gam[2] = {(const float*)d_in[7],  (const float*)d_in[13]};
    const float* bet[2] = {(const float*)d_in[8],  (const float*)d_in[14]};
    const int* src = ei;
    const int* dst = ei + NE;

    void *ph, *py, *pals, *pald, *pdeg, *prow, *pcur, *pcsr, *pbn, *psc, *psh;
    cudaGetSymbolAddress(&ph, g_h);
    cudaGetSymbolAddress(&py, g_y);
    cudaGetSymbolAddress(&pals, g_alS);
    cudaGetSymbolAddress(&pald, g_alD);
    cudaGetSymbolAddress(&pdeg, g_deg);
    cudaGetSymbolAddress(&prow, g_rowptr);
    cudaGetSymbolAddress(&pcur, g_cursor);
    cudaGetSymbolAddress(&pcsr, g_csr_src);
    cudaGetSymbolAddress(&pbn, g_bn);
    cudaGetSymbolAddress(&psc, g_scale);
    cudaGetSymbolAddress(&psh, g_shift);

    const int SM128 = 128 * (128 + 4) * 4 + NGRP * TM * 128 * 4;  // 67584+16384=83968
    const int SM32  = 128 * (32 + 4) * 4  + NGRP * TM * 32 * 4;   // 18432+4096 =22528
    cudaFuncSetAttribute(gemm_al<128>, cudaFuncAttributeMaxDynamicSharedMemorySize, SM128);
    cudaFuncSetAttribute(gemm_al<32>,  cudaFuncAttributeMaxDynamicSharedMemorySize, SM32);

    const int GEMM_BLOCKS = (NN + 63) / 64;       // 1563
    const int EB = (NE + 255) / 256;              // 6250
    const int GB = (NN * 32 + 255) / 256;         // 12500
    const int BB = (NN + 31) / 32;                // 3125

    // ---- CSR build (once; reused by all 3 layers) ----
    cudaMemsetAsync(pdeg, 0, NN * sizeof(int));
    hist_k<<<EB, 256>>>(dst, (int*)pdeg);
    scan_k<<<1, 1024>>>((const int*)pdeg, (int*)prow, (int*)pcur);
    scatter_build_k<<<EB, 256>>>(src, dst, (int*)pcur, (int*)pcsr);

    for (int L = 0; L < 3; ++L) {
        if (L == 0) {
            gemm_al<128><<<GEMM_BLOCKS, 256, SM128>>>(
                x, W[0], aS[0], aD[0], nullptr, nullptr,
                (float*)ph, (float*)pals, (float*)pald, 0);
        } else {
            gemm_al<32><<<GEMM_BLOCKS, 256, SM32>>>(
                (const float*)py, W[L], aS[L], aD[L],
                (const float*)psc, (const float*)psh,
                (float*)ph, (float*)pals, (float*)pald, 1);
        }

        float* dest = (L < 2) ? (float*)py : (float*)d_out;
        gather_k<<<GB, 256>>>((const int*)prow, (const int*)pcsr,
                              (const float4*)pals, (const float4*)pald,
                              (const float4*)ph, (const float4*)bia[L],
                              (float4*)dest);

        if (L < 2) {
            cudaMemsetAsync(pbn, 0, 2 * 32 * 32 * sizeof(float));
            bn_stats_k<<<BB, 1024>>>((const float*)py, (float*)pbn, (float*)pbn + 1024);
            bn_params_k<<<1, 32>>>((const float*)pbn, (const float*)pbn + 1024,
                                   gam[L], bet[L], (float*)psc, (float*)psh);
        }
    }

    cudaMemcpyAsync((float*)d_out + (size_t)NN * 32, ea,
                    (size_t)NE * 8 * sizeof(float), cudaMemcpyDeviceToDevice);
}

// round 9
// speedup vs baseline: 1.9231x; 1.0408x over previous
#include <cuda_runtime.h>
#include <cstdint>

#define NN 100000
#define NE 1600000
#define NEG_SLOPE 0.2f
#define BN_EPS 1e-5f

// ---------------- scratch (static __device__, no allocation) ----------------
__device__ __align__(16) float g_h[(size_t)NN * 128];   // GEMM output [N,4,32]
__device__ __align__(16) float g_y[(size_t)NN * 32];    // per-layer node features
__device__ __align__(16) float g_alS[(size_t)NN * 4];
__device__ __align__(16) float g_alD[(size_t)NN * 4];
__device__ int g_deg[NN];
__device__ int g_rowptr[NN + 1];
__device__ int g_cursor[NN];
__device__ int g_csr_src[NE];
__device__ float g_bn[2 * 32 * 32];                     // strided sums / sumsq
__device__ float g_scale[32];
__device__ float g_shift[32];

__device__ __forceinline__ float leaky(float e) {
    return e >= 0.f ? e : NEG_SLOPE * e;
}

// ---------------- CSR build ----------------
__global__ void hist_k(const int* __restrict__ dst, int* __restrict__ deg) {
    int i = blockIdx.x * blockDim.x + threadIdx.x;
    if (i < NE) atomicAdd(&deg[dst[i]], 1);
}

// single block, 1024 threads: chunked exclusive scan of deg -> rowptr, cursor
__global__ void scan_k(const int* __restrict__ deg, int* __restrict__ rowptr,
                       int* __restrict__ cursor) {
    __shared__ int sc[1024];
    const int tid = threadIdx.x;
    const int CH = (NN + 1023) / 1024;  // 98
    const int base = tid * CH;
    int s = 0;
    for (int i = 0; i < CH; ++i) {
        int idx = base + i;
        if (idx < NN) s += deg[idx];
    }
    sc[tid] = s;
    __syncthreads();
    for (int off = 1; off < 1024; off <<= 1) {
        int v = (tid >= off) ? sc[tid - off] : 0;
        __syncthreads();
        sc[tid] += v;
        __syncthreads();
    }
    int run = sc[tid] - s;
    for (int i = 0; i < CH; ++i) {
        int idx = base + i;
        if (idx < NN) {
            rowptr[idx] = run;
            cursor[idx] = run;
            run += deg[idx];
        }
    }
    if (tid == 1023) rowptr[NN] = sc[1023];
}

__global__ void scatter_build_k(const int* __restrict__ src, const int* __restrict__ dst,
                                int* __restrict__ cursor, int* __restrict__ csr_src) {
    int i = blockIdx.x * blockDim.x + threadIdx.x;
    if (i >= NE) return;
    int p = atomicAdd(&cursor[dst[i]], 1);
    csr_src[p] = src[i];
}

// ---------------- GEMM + attention logits (fused prev-layer BN+ReLU) ----------------
// 256 threads = 4 groups x 64. Thread computes 2 columns (c, c+64) x 8 nodes.
// W stored transposed in smem (pad stride F+4) so W reads are LDS.128.
#define TM 8
#define NGRP 4
template<int F>
__global__ void gemm_al(const float* __restrict__ x,     // [N,F]
                        const float* __restrict__ W,     // [F,128] (k-major)
                        const float* __restrict__ aS,    // [128]
                        const float* __restrict__ aD,    // [128]
                        const float* __restrict__ scale, // [F] or null
                        const float* __restrict__ shift, // [F] or null
                        float* __restrict__ h,           // [N,128]
                        float* __restrict__ alS,         // [N,4]
                        float* __restrict__ alD,         // [N,4]
                        int useBN)
{
    constexpr int FP = F + 4;                      // padded k-stride
    extern __shared__ float sm[];
    float* sWT = sm;                               // [128][FP] transposed W
    const int tid = threadIdx.x;
    const int c   = tid & 63;                      // column (and c+64)
    const int grp = tid >> 6;
    float* sx = sm + 128 * FP + grp * TM * F;      // per-group staging [TM][F]
    const int lane = tid & 31;
    const int h0 = c >> 5;                         // head of col c (0 or 1)

    // load W transposed: sWT[f*FP + k] = W[k*128 + f]
    for (int i = tid; i < F * 128; i += 256) {
        int k = i >> 7, f = i & 127;
        sWT[f * FP + k] = W[i];
    }
    const float as0 = aS[c],      ad0 = aD[c];
    const float as1 = aS[c + 64], ad1 = aD[c + 64];
    __syncthreads();

    const int nodeBase = blockIdx.x * 64;
    const float4* sx4  = reinterpret_cast<const float4*>(sx);
    const float4* sWT4 = reinterpret_cast<const float4*>(sWT);
    const int w0base = (c * FP) >> 2;
    const int w1base = ((c + 64) * FP) >> 2;

    for (int t = 0; t < 2; ++t) {
        int n0 = nodeBase + (t * NGRP + grp) * TM;
        __syncthreads();
        for (int i = c; i < TM * F; i += 64) {
            int m = i / F, k = i - m * F;
            int n = n0 + m;
            float v = 0.f;
            if (n < NN) {
                v = x[(size_t)n * F + k];
                if (useBN) v = fmaxf(fmaf(v, scale[k], shift[k]), 0.f);
            }
            sx[i] = v;
        }
        __syncthreads();

        float acc0[TM], acc1[TM];
#pragma unroll
        for (int m = 0; m < TM; ++m) { acc0[m] = 0.f; acc1[m] = 0.f; }

        for (int k = 0; k < F; k += 4) {
            float4 w0 = sWT4[w0base + (k >> 2)];
            float4 w1 = sWT4[w1base + (k >> 2)];
            float4 xv[TM];
#pragma unroll
            for (int m = 0; m < TM; ++m) xv[m] = sx4[(m * F + k) >> 2];
#pragma unroll
            for (int m = 0; m < TM; ++m) {
                acc0[m] = fmaf(xv[m].x, w0.x, acc0[m]);
                acc0[m] = fmaf(xv[m].y, w0.y, acc0[m]);
                acc0[m] = fmaf(xv[m].z, w0.z, acc0[m]);
                acc0[m] = fmaf(xv[m].w, w0.w, acc0[m]);
                acc1[m] = fmaf(xv[m].x, w1.x, acc1[m]);
                acc1[m] = fmaf(xv[m].y, w1.y, acc1[m]);
                acc1[m] = fmaf(xv[m].z, w1.z, acc1[m]);
                acc1[m] = fmaf(xv[m].w, w1.w, acc1[m]);
            }
        }

#pragma unroll
        for (int m = 0; m < TM; ++m) {
            int n = n0 + m;
            if (n < NN) {
                h[(size_t)n * 128 + c]      = acc0[m];
                h[(size_t)n * 128 + c + 64] = acc1[m];
            }
            float vs0 = acc0[m] * as0, vd0 = acc0[m] * ad0;
            float vs1 = acc1[m] * as1, vd1 = acc1[m] * ad1;
#pragma unroll
            for (int o = 16; o > 0; o >>= 1) {
                vs0 += __shfl_down_sync(0xffffffffu, vs0, o);
                vd0 += __shfl_down_sync(0xffffffffu, vd0, o);
                vs1 += __shfl_down_sync(0xffffffffu, vs1, o);
                vd1 += __shfl_down_sync(0xffffffffu, vd1, o);
            }
            if (lane == 0 && n < NN) {
                alS[n * 4 + h0]     = vs0;
                alD[n * 4 + h0]     = vd0;
                alS[n * 4 + h0 + 2] = vs1;
                alD[n * 4 + h0 + 2] = vd1;
            }
        }
    }
}

// ---------------- fused attention + aggregate + head-mean + bias ----------------
// Single-pass: accumulate unnormalized sum(ee * h[src]) and den simultaneously,
// scale by 0.25/den at the end. Exp computed ONCE per edge (4 heads at a time).
// Chunked: 32 edges staged per warp into smem (sid + ee4), then streamed —
// h[s] addresses come from smem broadcast, not dependent L2 loads.
__global__ void gather_k(const int* __restrict__ rowptr,
                         const int* __restrict__ csr_src,
                         const float4* __restrict__ alS4,  // [N] (4 heads)
                         const float4* __restrict__ alD4,  // [N]
                         const float4* __restrict__ h,     // [N,32] float4
                         const float4* __restrict__ bias4, // [8]
                         float4* __restrict__ out4)        // [N,8] float4
{
    __shared__ float4 s_ee[8][32];
    __shared__ int    s_sid[8][32];
    int gid = blockIdx.x * blockDim.x + threadIdx.x;
    int n = gid >> 5;
    if (n >= NN) return;
    const int warp = threadIdx.x >> 5;
    const int lane = gid & 31;
    const int head = lane >> 3;

    const int beg = rowptr[n];
    const int end = rowptr[n + 1];
    const float4 ad4 = alD4[n];   // broadcast load

    float4 den4 = make_float4(0.f, 0.f, 0.f, 0.f);
    float4 acc  = make_float4(0.f, 0.f, 0.f, 0.f);

    for (int base = beg; base < end; base += 32) {
        const int cnt = min(32, end - base);
        if (lane < cnt) {
            int s = csr_src[base + lane];
            float4 a = alS4[s];
            float4 ee;
            ee.x = __expf(leaky(a.x + ad4.x));
            ee.y = __expf(leaky(a.y + ad4.y));
            ee.z = __expf(leaky(a.z + ad4.z));
            ee.w = __expf(leaky(a.w + ad4.w));
            den4.x += ee.x; den4.y += ee.y; den4.z += ee.z; den4.w += ee.w;
            s_sid[warp][lane] = s;
            s_ee[warp][lane] = ee;
        }
        __syncwarp();
        for (int j = 0; j < cnt; ++j) {
            int s = s_sid[warp][j];                                // LDS broadcast
            float w = reinterpret_cast<const float*>(&s_ee[warp][j])[head];
            float4 hv = h[(size_t)s * 32 + lane];                  // streamed 128B
            acc.x = fmaf(w, hv.x, acc.x);
            acc.y = fmaf(w, hv.y, acc.y);
            acc.z = fmaf(w, hv.z, acc.z);
            acc.w = fmaf(w, hv.w, acc.w);
        }
        __syncwarp();
    }

    // reduce den across lanes (all 4 heads)
#pragma unroll
    for (int off = 16; off > 0; off >>= 1) {
        den4.x += __shfl_xor_sync(0xffffffffu, den4.x, off);
        den4.y += __shfl_xor_sync(0xffffffffu, den4.y, off);
        den4.z += __shfl_xor_sync(0xffffffffu, den4.z, off);
        den4.w += __shfl_xor_sync(0xffffffffu, den4.w, off);
    }
    const float den = (head == 0) ? den4.x : (head == 1) ? den4.y
                    : (head == 2) ? den4.z : den4.w;
    const float wsc = (den > 0.f) ? 0.25f / den : 0.f;
    acc.x *= wsc; acc.y *= wsc; acc.z *= wsc; acc.w *= wsc;

    // head mean: sum the 4 heads (lanes differing in bits 3,4)
#pragma unroll
    for (int off = 8; off <= 16; off <<= 1) {
        acc.x += __shfl_xor_sync(0xffffffffu, acc.x, off);
        acc.y += __shfl_xor_sync(0xffffffffu, acc.y, off);
        acc.z += __shfl_xor_sync(0xffffffffu, acc.z, off);
        acc.w += __shfl_xor_sync(0xffffffffu, acc.w, off);
    }

    if (lane < 8) {
        float4 b = bias4[lane];
        float4 r;
        r.x = acc.x + b.x; r.y = acc.y + b.y;
        r.z = acc.z + b.z; r.w = acc.w + b.w;
        out4[(size_t)n * 8 + lane] = r;
    }
}

// ---------------- BN stats over y ----------------
__global__ void bn_stats_k(const float* __restrict__ y,
                           float* __restrict__ bnsum, float* __restrict__ bnsq)
{
    __shared__ float s1[1024];
    __shared__ float s2[1024];
    int tid = threadIdx.x;
    int c = tid & 31;
    int n = blockIdx.x * 32 + (tid >> 5);
    float val = (n < NN) ? y[(size_t)n * 32 + c] : 0.f;
    s1[tid] = val;
    s2[tid] = val * val;
    __syncthreads();
    for (int st = 512; st >= 32; st >>= 1) {
        if (tid < st) { s1[tid] += s1[tid + st]; s2[tid] += s2[tid + st]; }
        __syncthreads();
    }
    if (tid < 32) {
        atomicAdd(&bnsum[tid * 32], s1[tid]);
        atomicAdd(&bnsq[tid * 32], s2[tid]);
    }
}

__global__ void bn_params_k(const float* __restrict__ bnsum, const float* __restrict__ bnsq,
                            const float* __restrict__ g, const float* __restrict__ be,
                            float* __restrict__ scale, float* __restrict__ shift)
{
    int c = threadIdx.x;
    if (c >= 32) return;
    float mu = bnsum[c * 32] * (1.f / NN);
    float var = bnsq[c * 32] * (1.f / NN) - mu * mu;
    float sc = g[c] * rsqrtf(var + BN_EPS);
    scale[c] = sc;
    shift[c] = be[c] - mu * sc;
}

// ---------------- host ----------------
extern "C" void kernel_launch(void* const* d_in, const int* in_sizes, int n_in,
                              void* d_out, int out_size)
{
    const float* x   = (const float*)d_in[0];
    const int*   ei  = (const int*)  d_in[1];
    const float* ea  = (const float*)d_in[2];
    const float* W[3]   = {(const float*)d_in[3],  (const float*)d_in[9],  (const float*)d_in[15]};
    const float* aS[3]  = {(const float*)d_in[4],  (const float*)d_in[10], (const float*)d_in[16]};
    const float* aD[3]  = {(const float*)d_in[5],  (const float*)d_in[11], (const float*)d_in[17]};
    const float* bia[3] = {(const float*)d_in[6],  (const float*)d_in[12], (const float*)d_in[18]};
    const float* gam[2] = {(const float*)d_in[7],  (const float*)d_in[13]};
    const float* bet[2] = {(const float*)d_in[8],  (const float*)d_in[14]};
    const int* src = ei;
    const int* dst = ei + NE;

    void *ph, *py, *pals, *pald, *pdeg, *prow, *pcur, *pcsr, *pbn, *psc, *psh;
    cudaGetSymbolAddress(&ph, g_h);
    cudaGetSymbolAddress(&py, g_y);
    cudaGetSymbolAddress(&pals, g_alS);
    cudaGetSymbolAddress(&pald, g_alD);
    cudaGetSymbolAddress(&pdeg, g_deg);
    cudaGetSymbolAddress(&prow, g_rowptr);
    cudaGetSymbolAddress(&pcur, g_cursor);
    cudaGetSymbolAddress(&pcsr, g_csr_src);
    cudaGetSymbolAddress(&pbn, g_bn);
    cudaGetSymbolAddress(&psc, g_scale);
    cudaGetSymbolAddress(&psh, g_shift);

    const int SM128 = 128 * (128 + 4) * 4 + NGRP * TM * 128 * 4;  // 83968
    const int SM32  = 128 * (32 + 4) * 4  + NGRP * TM * 32 * 4;   // 22528
    cudaFuncSetAttribute(gemm_al<128>, cudaFuncAttributeMaxDynamicSharedMemorySize, SM128);
    cudaFuncSetAttribute(gemm_al<32>,  cudaFuncAttributeMaxDynamicSharedMemorySize, SM32);

    const int GEMM_BLOCKS = (NN + 63) / 64;       // 1563
    const int EB = (NE + 255) / 256;              // 6250
    const int GB = (NN * 32 + 255) / 256;         // 12500
    const int BB = (NN + 31) / 32;                // 3125

    // ---- CSR build (once; reused by all 3 layers) ----
    cudaMemsetAsync(pdeg, 0, NN * sizeof(int));
    hist_k<<<EB, 256>>>(dst, (int*)pdeg);
    scan_k<<<1, 1024>>>((const int*)pdeg, (int*)prow, (int*)pcur);
    scatter_build_k<<<EB, 256>>>(src, dst, (int*)pcur, (int*)pcsr);

    for (int L = 0; L < 3; ++L) {
        if (L == 0) {
            gemm_al<128><<<GEMM_BLOCKS, 256, SM128>>>(
                x, W[0], aS[0], aD[0], nullptr, nullptr,
                (float*)ph, (float*)pals, (float*)pald, 0);
        } else {
            gemm_al<32><<<GEMM_BLOCKS, 256, SM32>>>(
                (const float*)py, W[L], aS[L], aD[L],
                (const float*)psc, (const float*)psh,
                (float*)ph, (float*)pals, (float*)pald, 1);
        }

        float* dest = (L < 2) ? (float*)py : (float*)d_out;
        gather_k<<<GB, 256>>>((const int*)prow, (const int*)pcsr,
                              (const float4*)pals, (const float4*)pald,
                              (const float4*)ph, (const float4*)bia[L],
                              (float4*)dest);

        if (L < 2) {
            cudaMemsetAsync(pbn, 0, 2 * 32 * 32 * sizeof(float));
            bn_stats_k<<<BB, 1024>>>((const float*)py, (float*)pbn, (float*)pbn + 1024);
            bn_params_k<<<1, 32>>>((const float*)pbn, (const float*)pbn + 1024,
                                   gam[L], bet[L], (float*)psc, (float*)psh);
        }
    }

    cudaMemcpyAsync((float*)d_out + (size_t)NN * 32, ea,
                    (size_t)NE * 8 * sizeof(float), cudaMemcpyDeviceToDevice);
}

// round 12
// speedup vs baseline: 2.1936x; 1.1407x over previous
#include <cuda_runtime.h>
#include <cstdint>

#define NN 100000
#define NE 1600000
#define NEG_SLOPE 0.2f
#define BN_EPS 1e-5f

// ---------------- scratch (static __device__, no allocation) ----------------
__device__ __align__(16) float g_h[(size_t)NN * 128];   // GEMM output [N,4,32]
__device__ __align__(16) float g_y[(size_t)NN * 32];    // per-layer node features
__device__ __align__(16) float g_alS[(size_t)NN * 4];
__device__ __align__(16) float g_alD[(size_t)NN * 4];
__device__ int g_deg[NN];
__device__ int g_rowptr[NN + 1];
__device__ int g_cursor[NN];
__device__ int g_csr_src[NE];
__device__ float g_bn[2 * 32 * 32];                     // strided sums / sumsq
__device__ float g_scale[32];
__device__ float g_shift[32];

__device__ __forceinline__ float leaky(float e) {
    return e >= 0.f ? e : NEG_SLOPE * e;
}

// ---------------- CSR build ----------------
__global__ void hist_k(const int* __restrict__ dst, int* __restrict__ deg) {
    int i = blockIdx.x * blockDim.x + threadIdx.x;
    if (i < NE) atomicAdd(&deg[dst[i]], 1);
}

// single block, 1024 threads: chunked exclusive scan of deg -> rowptr, cursor
__global__ void scan_k(const int* __restrict__ deg, int* __restrict__ rowptr,
                       int* __restrict__ cursor) {
    __shared__ int sc[1024];
    const int tid = threadIdx.x;
    const int CH = (NN + 1023) / 1024;  // 98
    const int base = tid * CH;
    int s = 0;
    for (int i = 0; i < CH; ++i) {
        int idx = base + i;
        if (idx < NN) s += deg[idx];
    }
    sc[tid] = s;
    __syncthreads();
    for (int off = 1; off < 1024; off <<= 1) {
        int v = (tid >= off) ? sc[tid - off] : 0;
        __syncthreads();
        sc[tid] += v;
        __syncthreads();
    }
    int run = sc[tid] - s;
    for (int i = 0; i < CH; ++i) {
        int idx = base + i;
        if (idx < NN) {
            rowptr[idx] = run;
            cursor[idx] = run;
            run += deg[idx];
        }
    }
    if (tid == 1023) rowptr[NN] = sc[1023];
}

__global__ void scatter_build_k(const int* __restrict__ src, const int* __restrict__ dst,
                                int* __restrict__ cursor, int* __restrict__ csr_src) {
    int i = blockIdx.x * blockDim.x + threadIdx.x;
    if (i >= NE) return;
    int p = atomicAdd(&cursor[dst[i]], 1);
    csr_src[p] = src[i];
}

// ---------------- GEMM + attention logits (fused prev-layer BN+ReLU) ----------------
// Register-blocked: 128x128 tile, 256 threads (16x16), 8x8 micro-tile per thread.
// K chunked by 32. As transposed [k][m], Bs [k][n]. FMA-bound inner loop.
template<int F>
__global__ void gemm_al(const float* __restrict__ x,     // [N,F]
                        const float* __restrict__ W,     // [F,128] (k-major)
                        const float* __restrict__ aS,    // [128]
                        const float* __restrict__ aD,    // [128]
                        const float* __restrict__ scale, // [F] or null
                        const float* __restrict__ shift, // [F] or null
                        float* __restrict__ h,           // [N,128]
                        float* __restrict__ alS,         // [N,4]
                        float* __restrict__ alD,         // [N,4]
                        int useBN)
{
    __shared__ float As[32][132];   // [k][m], row 16B-aligned (132*4 % 16 == 0)
    __shared__ float Bs[32][132];   // [k][n]
    const int tid = threadIdx.x;
    const int tx = tid & 15;
    const int ty = tid >> 4;
    const int n0 = blockIdx.x * 128;
    const int col0 = tx * 8;

    const int ar = tid >> 1;          // A-load row 0..127
    const int ah = (tid & 1) * 16;    // A-load k-half offset
    const int bk = tid >> 3;          // B-load k 0..31
    const int bs = (tid & 7) * 16;    // B-load col segment

    float acc[8][8];
#pragma unroll
    for (int i = 0; i < 8; ++i)
#pragma unroll
        for (int j = 0; j < 8; ++j) acc[i][j] = 0.f;

    for (int k0 = 0; k0 < F; k0 += 32) {
        // ---- A load (transpose into As[k][m]), fused BN+ReLU ----
        {
            int n = n0 + ar;
            const float* xp = x + (size_t)n * F + k0 + ah;
#pragma unroll
            for (int q = 0; q < 4; ++q) {
                float4 v = make_float4(0.f, 0.f, 0.f, 0.f);
                if (n < NN) {
                    v = *(const float4*)(xp + q * 4);
                    if (useBN) {
                        int k = k0 + ah + q * 4;
                        v.x = fmaxf(fmaf(v.x, scale[k],     shift[k]),     0.f);
                        v.y = fmaxf(fmaf(v.y, scale[k + 1], shift[k + 1]), 0.f);
                        v.z = fmaxf(fmaf(v.z, scale[k + 2], shift[k + 2]), 0.f);
                        v.w = fmaxf(fmaf(v.w, scale[k + 3], shift[k + 3]), 0.f);
                    }
                }
                As[ah + q * 4 + 0][ar] = v.x;
                As[ah + q * 4 + 1][ar] = v.y;
                As[ah + q * 4 + 2][ar] = v.z;
                As[ah + q * 4 + 3][ar] = v.w;
            }
        }
        // ---- B load (direct copy into Bs[k][n]) ----
        {
            const float* wp = W + (size_t)(k0 + bk) * 128 + bs;
#pragma unroll
            for (int q = 0; q < 4; ++q)
                *(float4*)&Bs[bk][bs + q * 4] = *(const float4*)(wp + q * 4);
        }
        __syncthreads();

#pragma unroll 4
        for (int k = 0; k < 32; ++k) {
            float4 a0 = *(const float4*)&As[k][ty * 8];
            float4 a1 = *(const float4*)&As[k][ty * 8 + 4];
            float4 b0 = *(const float4*)&Bs[k][col0];
            float4 b1 = *(const float4*)&Bs[k][col0 + 4];
            float a[8] = {a0.x, a0.y, a0.z, a0.w, a1.x, a1.y, a1.z, a1.w};
            float b[8] = {b0.x, b0.y, b0.z, b0.w, b1.x, b1.y, b1.z, b1.w};
#pragma unroll
            for (int i = 0; i < 8; ++i)
#pragma unroll
                for (int j = 0; j < 8; ++j)
                    acc[i][j] = fmaf(a[i], b[j], acc[i][j]);
        }
        __syncthreads();
    }

    // ---- epilogue: h stores + fused attention logits ----
    float4 s0 = *(const float4*)(aS + col0);
    float4 s1 = *(const float4*)(aS + col0 + 4);
    float4 d0 = *(const float4*)(aD + col0);
    float4 d1 = *(const float4*)(aD + col0 + 4);
    float aSv[8] = {s0.x, s0.y, s0.z, s0.w, s1.x, s1.y, s1.z, s1.w};
    float aDv[8] = {d0.x, d0.y, d0.z, d0.w, d1.x, d1.y, d1.z, d1.w};

#pragma unroll
    for (int i = 0; i < 8; ++i) {
        int n = n0 + ty * 8 + i;
        bool ok = (n < NN);
        if (ok) {
            *(float4*)&h[(size_t)n * 128 + col0] =
                make_float4(acc[i][0], acc[i][1], acc[i][2], acc[i][3]);
            *(float4*)&h[(size_t)n * 128 + col0 + 4] =
                make_float4(acc[i][4], acc[i][5], acc[i][6], acc[i][7]);
        }
        float vs = 0.f, vd = 0.f;
#pragma unroll
        for (int j = 0; j < 8; ++j) {
            vs = fmaf(acc[i][j], aSv[j], vs);
            vd = fmaf(acc[i][j], aDv[j], vd);
        }
        // reduce over the 4 tx-groups of one head (same-ty lanes differ in lane bits 0..3)
        vs += __shfl_xor_sync(0xffffffffu, vs, 1);
        vd += __shfl_xor_sync(0xffffffffu, vd, 1);
        vs += __shfl_xor_sync(0xffffffffu, vs, 2);
        vd += __shfl_xor_sync(0xffffffffu, vd, 2);
        if ((tx & 3) == 0 && ok) {
            alS[n * 4 + (tx >> 2)] = vs;
            alD[n * 4 + (tx >> 2)] = vd;
        }
    }
}

// ---------------- fused attention + aggregate + head-mean + bias ----------------
// Single-pass: accumulate unnormalized sum(ee * h[src]) and den simultaneously,
// scale by 0.25/den at the end. Exp computed ONCE per edge (4 heads at a time).
__global__ void gather_k(const int* __restrict__ rowptr,
                         const int* __restrict__ csr_src,
                         const float4* __restrict__ alS4,  // [N] (4 heads)
                         const float4* __restrict__ alD4,  // [N]
                         const float4* __restrict__ h,     // [N,32] float4
                         const float4* __restrict__ bias4, // [8]
                         float4* __restrict__ out4)        // [N,8] float4
{
    __shared__ float4 s_ee[8][32];
    __shared__ int    s_sid[8][32];
    int gid = blockIdx.x * blockDim.x + threadIdx.x;
    int n = gid >> 5;
    if (n >= NN) return;
    const int warp = threadIdx.x >> 5;
    const int lane = gid & 31;
    const int head = lane >> 3;

    const int beg = rowptr[n];
    const int end = rowptr[n + 1];
    const float4 ad4 = alD4[n];   // broadcast load

    float4 den4 = make_float4(0.f, 0.f, 0.f, 0.f);
    float4 acc  = make_float4(0.f, 0.f, 0.f, 0.f);

    for (int base = beg; base < end; base += 32) {
        const int cnt = min(32, end - base);
        if (lane < cnt) {
            int s = csr_src[base + lane];
            float4 a = alS4[s];
            float4 ee;
            ee.x = __expf(leaky(a.x + ad4.x));
            ee.y = __expf(leaky(a.y + ad4.y));
            ee.z = __expf(leaky(a.z + ad4.z));
            ee.w = __expf(leaky(a.w + ad4.w));
            den4.x += ee.x; den4.y += ee.y; den4.z += ee.z; den4.w += ee.w;
            s_sid[warp][lane] = s;
            s_ee[warp][lane] = ee;
        }
        __syncwarp();
        for (int j = 0; j < cnt; ++j) {
            int s = s_sid[warp][j];                                // LDS broadcast
            float w = reinterpret_cast<const float*>(&s_ee[warp][j])[head];
            float4 hv = h[(size_t)s * 32 + lane];                  // streamed 128B
            acc.x = fmaf(w, hv.x, acc.x);
            acc.y = fmaf(w, hv.y, acc.y);
            acc.z = fmaf(w, hv.z, acc.z);
            acc.w = fmaf(w, hv.w, acc.w);
        }
        __syncwarp();
    }

    // reduce den across lanes (all 4 heads)
#pragma unroll
    for (int off = 16; off > 0; off >>= 1) {
        den4.x += __shfl_xor_sync(0xffffffffu, den4.x, off);
        den4.y += __shfl_xor_sync(0xffffffffu, den4.y, off);
        den4.z += __shfl_xor_sync(0xffffffffu, den4.z, off);
        den4.w += __shfl_xor_sync(0xffffffffu, den4.w, off);
    }
    const float den = (head == 0) ? den4.x : (head == 1) ? den4.y
                    : (head == 2) ? den4.z : den4.w;
    const float wsc = (den > 0.f) ? 0.25f / den : 0.f;
    acc.x *= wsc; acc.y *= wsc; acc.z *= wsc; acc.w *= wsc;

    // head mean: sum the 4 heads (lanes differing in bits 3,4)
#pragma unroll
    for (int off = 8; off <= 16; off <<= 1) {
        acc.x += __shfl_xor_sync(0xffffffffu, acc.x, off);
        acc.y += __shfl_xor_sync(0xffffffffu, acc.y, off);
        acc.z += __shfl_xor_sync(0xffffffffu, acc.z, off);
        acc.w += __shfl_xor_sync(0xffffffffu, acc.w, off);
    }

    if (lane < 8) {
        float4 b = bias4[lane];
        float4 r;
        r.x = acc.x + b.x; r.y = acc.y + b.y;
        r.z = acc.z + b.z; r.w = acc.w + b.w;
        out4[(size_t)n * 8 + lane] = r;
    }
}

// ---------------- BN stats over y ----------------
__global__ void bn_stats_k(const float* __restrict__ y,
                           float* __restrict__ bnsum, float* __restrict__ bnsq)
{
    __shared__ float s1[1024];
    __shared__ float s2[1024];
    int tid = threadIdx.x;
    int c = tid & 31;
    int n = blockIdx.x * 32 + (tid >> 5);
    float val = (n < NN) ? y[(size_t)n * 32 + c] : 0.f;
    s1[tid] = val;
    s2[tid] = val * val;
    __syncthreads();
    for (int st = 512; st >= 32; st >>= 1) {
        if (tid < st) { s1[tid] += s1[tid + st]; s2[tid] += s2[tid + st]; }
        __syncthreads();
    }
    if (tid < 32) {
        atomicAdd(&bnsum[tid * 32], s1[tid]);
        atomicAdd(&bnsq[tid * 32], s2[tid]);
    }
}

__global__ void bn_params_k(const float* __restrict__ bnsum, const float* __restrict__ bnsq,
                            const float* __restrict__ g, const float* __restrict__ be,
                            float* __restrict__ scale, float* __restrict__ shift)
{
    int c = threadIdx.x;
    if (c >= 32) return;
    float mu = bnsum[c * 32] * (1.f / NN);
    float var = bnsq[c * 32] * (1.f / NN) - mu * mu;
    float sc = g[c] * rsqrtf(var + BN_EPS);
    scale[c] = sc;
    shift[c] = be[c] - mu * sc;
}

// ---------------- host ----------------
extern "C" void kernel_launch(void* const* d_in, const int* in_sizes, int n_in,
                              void* d_out, int out_size)
{
    const float* x   = (const float*)d_in[0];
    const int*   ei  = (const int*)  d_in[1];
    const float* ea  = (const float*)d_in[2];
    const float* W[3]   = {(const float*)d_in[3],  (const float*)d_in[9],  (const float*)d_in[15]};
    const float* aS[3]  = {(const float*)d_in[4],  (const float*)d_in[10], (const float*)d_in[16]};
    const float* aD[3]  = {(const float*)d_in[5],  (const float*)d_in[11], (const float*)d_in[17]};
    const float* bia[3] = {(const float*)d_in[6],  (const float*)d_in[12], (const float*)d_in[18]};
    const float* gam[2] = {(const float*)d_in[7],  (const float*)d_in[13]};
    const float* bet[2] = {(const float*)d_in[8],  (const float*)d_in[14]};
    const int* src = ei;
    const int* dst = ei + NE;

    void *ph, *py, *pals, *pald, *pdeg, *prow, *pcur, *pcsr, *pbn, *psc, *psh;
    cudaGetSymbolAddress(&ph, g_h);
    cudaGetSymbolAddress(&py, g_y);
    cudaGetSymbolAddress(&pals, g_alS);
    cudaGetSymbolAddress(&pald, g_alD);
    cudaGetSymbolAddress(&pdeg, g_deg);
    cudaGetSymbolAddress(&prow, g_rowptr);
    cudaGetSymbolAddress(&pcur, g_cursor);
    cudaGetSymbolAddress(&pcsr, g_csr_src);
    cudaGetSymbolAddress(&pbn, g_bn);
    cudaGetSymbolAddress(&psc, g_scale);
    cudaGetSymbolAddress(&psh, g_shift);

    const int GEMM_BLOCKS = (NN + 127) / 128;     // 782
    const int EB = (NE + 255) / 256;              // 6250
    const int GB = (NN * 32 + 255) / 256;         // 12500
    const int BB = (NN + 31) / 32;                // 3125

    // ---- CSR build (once; reused by all 3 layers) ----
    cudaMemsetAsync(pdeg, 0, NN * sizeof(int));
    hist_k<<<EB, 256>>>(dst, (int*)pdeg);
    scan_k<<<1, 1024>>>((const int*)pdeg, (int*)prow, (int*)pcur);
    scatter_build_k<<<EB, 256>>>(src, dst, (int*)pcur, (int*)pcsr);

    for (int L = 0; L < 3; ++L) {
        if (L == 0) {
            gemm_al<128><<<GEMM_BLOCKS, 256>>>(
                x, W[0], aS[0], aD[0], nullptr, nullptr,
                (float*)ph, (float*)pals, (float*)pald, 0);
        } else {
            gemm_al<32><<<GEMM_BLOCKS, 256>>>(
                (const float*)py, W[L], aS[L], aD[L],
                (const float*)psc, (const float*)psh,
                (float*)ph, (float*)pals, (float*)pald, 1);
        }

        float* dest = (L < 2) ? (float*)py : (float*)d_out;
        gather_k<<<GB, 256>>>((const int*)prow, (const int*)pcsr,
                              (const float4*)pals, (const float4*)pald,
                              (const float4*)ph, (const float4*)bia[L],
                              (float4*)dest);

        if (L < 2) {
            cudaMemsetAsync(pbn, 0, 2 * 32 * 32 * sizeof(float));
            bn_stats_k<<<BB, 1024>>>((const float*)py, (float*)pbn, (float*)pbn + 1024);
            bn_params_k<<<1, 32>>>((const float*)pbn, (const float*)pbn + 1024,
                                   gam[L], bet[L], (float*)psc, (float*)psh);
        }
    }

    cudaMemcpyAsync((float*)d_out + (size_t)NN * 32, ea,
                    (size_t)NE * 8 * sizeof(float), cudaMemcpyDeviceToDevice);
}